// round 1
// baseline (speedup 1.0000x reference)
#include <cuda_runtime.h>
#include <cuda_bf16.h>
#include <cstdint>
#include <cstdio>

#define HQ     32
#define HKV    8
#define DHEAD  128
#define BLK    128
#define QSTR   132   // Q/K/P smem row stride (floats): conflict-free frag loads
#define VSTR   136   // V smem row stride: conflict-free B-frag loads for PV
#define NTHREADS 256

#define OFF_K (BLK*QSTR)
#define OFF_V (OFF_K + BLK*QSTR)
#define SMEM_FLOATS (OFF_V + BLK*VSTR)
#define SMEM_BYTES (SMEM_FLOATS * 4)   // 204800 B

__device__ __forceinline__ float f2tf32(float x) {
    uint32_t u;
    asm("cvt.rna.tf32.f32 %0, %1;" : "=r"(u) : "f"(x));
    return __uint_as_float(u);
}

__device__ __forceinline__ void mma_tf32(float d[4], const uint32_t a[4], const uint32_t b[2]) {
    asm volatile(
        "mma.sync.aligned.m16n8k8.row.col.f32.tf32.tf32.f32 "
        "{%0,%1,%2,%3}, {%4,%5,%6,%7}, {%8,%9}, {%0,%1,%2,%3};\n"
        : "+f"(d[0]), "+f"(d[1]), "+f"(d[2]), "+f"(d[3])
        : "r"(a[0]), "r"(a[1]), "r"(a[2]), "r"(a[3]),
          "r"(b[0]), "r"(b[1]));
}

// Load a 128x128 fp32 tile gmem->smem with tf32 rounding (and optional scale).
__device__ __forceinline__ void ldtile(float* __restrict__ dst, int dstride,
                                       const float* __restrict__ src, int sstride,
                                       int tid, float mul) {
    const int r0 = tid >> 5;
    const int c  = (tid & 31) << 2;
#pragma unroll
    for (int it = 0; it < 16; ++it) {
        const int row = (it << 3) + r0;
        const float4 v = *reinterpret_cast<const float4*>(src + (size_t)row * sstride + c);
        float4 w;
        w.x = f2tf32(v.x * mul);
        w.y = f2tf32(v.y * mul);
        w.z = f2tf32(v.z * mul);
        w.w = f2tf32(v.w * mul);
        *reinterpret_cast<float4*>(dst + row * dstride + c) = w;
    }
}

// Process one 128-key chunk: S = Q K^T (masked), online softmax update, O += P V.
// CHUNK==0: keys block n-1, valid iff key_col >  query_row  (tiles [wb/8, 16))
// CHUNK==1: keys block n,   valid iff key_col <= query_row  (tiles [0, wb/8+2))
template <int CHUNK>
__device__ __forceinline__ void process_chunk(
    const float* __restrict__ Qs, float* __restrict__ Ks, const float* __restrict__ Vs,
    float (&o)[16][4], float& m0, float& m1, float& l0, float& l1,
    int wb, int gq, int tig)
{
    const int tb  = wb >> 3;
    const int tlo = (CHUNK == 0) ? tb : 0;
    const int thi = (CHUNK == 0) ? 16 : (tb + 2);

    float sacc[16][4];
#pragma unroll
    for (int t = 0; t < 16; ++t) {
        if (t < tlo || t >= thi) continue;
        sacc[t][0] = sacc[t][1] = sacc[t][2] = sacc[t][3] = 0.f;
    }

    const int r0 = wb + gq;
    const int r1 = r0 + 8;
    const int arow0 = r0 * QSTR;
    const int arow1 = r1 * QSTR;

    // ---- S = Q @ K^T ----
#pragma unroll 4
    for (int kk = 0; kk < 16; ++kk) {
        const int ac = (kk << 3) + tig;
        uint32_t a[4];
        a[0] = __float_as_uint(Qs[arow0 + ac]);
        a[1] = __float_as_uint(Qs[arow1 + ac]);
        a[2] = __float_as_uint(Qs[arow0 + ac + 4]);
        a[3] = __float_as_uint(Qs[arow1 + ac + 4]);
#pragma unroll
        for (int t = 0; t < 16; ++t) {
            if (t < tlo || t >= thi) continue;
            const int br = ((t << 3) + gq) * QSTR + ac;
            uint32_t bf[2];
            bf[0] = __float_as_uint(Ks[br]);
            bf[1] = __float_as_uint(Ks[br + 4]);
            mma_tf32(sacc[t], a, bf);
        }
    }

    // ---- mask + row max ----
    float rmax0 = -1e30f, rmax1 = -1e30f;
#pragma unroll
    for (int t = 0; t < 16; ++t) {
        if (t < tlo || t >= thi) continue;
        const int cb = (t << 3) + (tig << 1);
#pragma unroll
        for (int e = 0; e < 2; ++e) {
            const int col = cb + e;
            const bool v0 = (CHUNK == 0) ? (col > r0) : (col <= r0);
            const bool v1 = (CHUNK == 0) ? (col > r1) : (col <= r1);
            if (!v0) sacc[t][e]     = -1e30f;
            if (!v1) sacc[t][2 + e] = -1e30f;
            rmax0 = fmaxf(rmax0, sacc[t][e]);
            rmax1 = fmaxf(rmax1, sacc[t][2 + e]);
        }
    }
    rmax0 = fmaxf(rmax0, __shfl_xor_sync(0xffffffffu, rmax0, 1));
    rmax0 = fmaxf(rmax0, __shfl_xor_sync(0xffffffffu, rmax0, 2));
    rmax1 = fmaxf(rmax1, __shfl_xor_sync(0xffffffffu, rmax1, 1));
    rmax1 = fmaxf(rmax1, __shfl_xor_sync(0xffffffffu, rmax1, 2));

    const float mn0 = fmaxf(m0, rmax0);
    const float mn1 = fmaxf(m1, rmax1);
    const float c0 = __expf(m0 - mn0);   // __expf(-inf)=0: wipes fully-masked history
    const float c1 = __expf(m1 - mn1);
    m0 = mn0; m1 = mn1;
    l0 *= c0; l1 *= c1;
#pragma unroll
    for (int t = 0; t < 16; ++t) {
        o[t][0] *= c0; o[t][1] *= c0;
        o[t][2] *= c1; o[t][3] *= c1;
    }

    float s0 = 0.f, s1 = 0.f;
#pragma unroll
    for (int t = 0; t < 16; ++t) {
        if (t < tlo || t >= thi) continue;
        sacc[t][0] = __expf(sacc[t][0] - mn0);
        sacc[t][1] = __expf(sacc[t][1] - mn0);
        sacc[t][2] = __expf(sacc[t][2] - mn1);
        sacc[t][3] = __expf(sacc[t][3] - mn1);
        s0 += sacc[t][0] + sacc[t][1];
        s1 += sacc[t][2] + sacc[t][3];
    }
    l0 += s0; l1 += s1;

    // ---- P -> smem (reuse K buffer); accumulator layout -> A-fragment layout ----
    __syncthreads();   // all warps finished reading K
#pragma unroll
    for (int t = 0; t < 16; ++t) {
        if (t < tlo || t >= thi) continue;
        const int cb = (t << 3) + (tig << 1);
        *reinterpret_cast<float2*>(&Ks[r0 * QSTR + cb]) =
            make_float2(f2tf32(sacc[t][0]), f2tf32(sacc[t][1]));
        *reinterpret_cast<float2*>(&Ks[r1 * QSTR + cb]) =
            make_float2(f2tf32(sacc[t][2]), f2tf32(sacc[t][3]));
    }
    __syncthreads();

    // ---- O += P @ V ----
#pragma unroll 4
    for (int ks = 0; ks < 16; ++ks) {
        if (ks < tlo || ks >= thi) continue;
        const int pc = (ks << 3) + tig;
        uint32_t a[4];
        a[0] = __float_as_uint(Ks[arow0 + pc]);
        a[1] = __float_as_uint(Ks[arow1 + pc]);
        a[2] = __float_as_uint(Ks[arow0 + pc + 4]);
        a[3] = __float_as_uint(Ks[arow1 + pc + 4]);
        const int vrow = ((ks << 3) + tig) * VSTR;
#pragma unroll
        for (int t = 0; t < 16; ++t) {
            const int vb = vrow + (t << 3) + gq;
            uint32_t bf[2];
            bf[0] = __float_as_uint(Vs[vb]);
            bf[1] = __float_as_uint(Vs[vb + 4 * VSTR]);
            mma_tf32(o[t], a, bf);
        }
    }
}

__global__ void __launch_bounds__(NTHREADS, 1)
fa_swa_kernel(const float* __restrict__ Q, const float* __restrict__ K,
              const float* __restrict__ V, float* __restrict__ Out, int S)
{
    extern __shared__ float sm[];
    float* Qs = sm;
    float* Ks = sm + OFF_K;
    float* Vs = sm + OFF_V;

    const int n   = blockIdx.x;
    const int hq  = blockIdx.y;
    const int b   = blockIdx.z;
    const int hkv = hq >> 2;     // g = HQ/HKV = 4

    const int tid  = threadIdx.x;
    const int warp = tid >> 5;
    const int lane = tid & 31;
    const int wb   = warp << 4;  // 16 query rows per warp
    const int gq   = lane >> 2;
    const int tig  = lane & 3;

    const float scale = 0.08838834764831845f;  // 1/sqrt(128)

    const float* Qp = Q + ((size_t)(b * S + n * BLK) * HQ + hq) * DHEAD;
    ldtile(Qs, QSTR, Qp, HQ * DHEAD, tid, scale);

    float o[16][4];
#pragma unroll
    for (int t = 0; t < 16; ++t)
        o[t][0] = o[t][1] = o[t][2] = o[t][3] = 0.f;
    float m0 = -INFINITY, m1 = -INFINITY, l0 = 0.f, l1 = 0.f;

    if (n > 0) {
        const int key0 = (n - 1) * BLK;
        const float* Kp = K + ((size_t)(b * S + key0) * HKV + hkv) * DHEAD;
        const float* Vp = V + ((size_t)(b * S + key0) * HKV + hkv) * DHEAD;
        ldtile(Ks, QSTR, Kp, HKV * DHEAD, tid, 1.f);
        ldtile(Vs, VSTR, Vp, HKV * DHEAD, tid, 1.f);
        __syncthreads();
        process_chunk<0>(Qs, Ks, Vs, o, m0, m1, l0, l1, wb, gq, tig);
        __syncthreads();   // chunk0 PV done reading Ks/Vs before overwrite
    }
    {
        const int key0 = n * BLK;
        const float* Kp = K + ((size_t)(b * S + key0) * HKV + hkv) * DHEAD;
        const float* Vp = V + ((size_t)(b * S + key0) * HKV + hkv) * DHEAD;
        ldtile(Ks, QSTR, Kp, HKV * DHEAD, tid, 1.f);
        ldtile(Vs, VSTR, Vp, HKV * DHEAD, tid, 1.f);
        __syncthreads();
        process_chunk<1>(Qs, Ks, Vs, o, m0, m1, l0, l1, wb, gq, tig);
    }

    // finalize: reduce l across the quad, normalize, store
    l0 += __shfl_xor_sync(0xffffffffu, l0, 1);
    l0 += __shfl_xor_sync(0xffffffffu, l0, 2);
    l1 += __shfl_xor_sync(0xffffffffu, l1, 1);
    l1 += __shfl_xor_sync(0xffffffffu, l1, 2);
    const float inv0 = 1.f / l0;
    const float inv1 = 1.f / l1;

    float* Op = Out + ((size_t)(b * S + n * BLK) * HQ + hq) * DHEAD;
    const size_t rstride = (size_t)HQ * DHEAD;
    const int r0 = wb + gq, r1 = r0 + 8;
#pragma unroll
    for (int t = 0; t < 16; ++t) {
        const int cb = (t << 3) + (tig << 1);
        *reinterpret_cast<float2*>(Op + (size_t)r0 * rstride + cb) =
            make_float2(o[t][0] * inv0, o[t][1] * inv0);
        *reinterpret_cast<float2*>(Op + (size_t)r1 * rstride + cb) =
            make_float2(o[t][2] * inv1, o[t][3] * inv1);
    }
}

extern "C" void kernel_launch(void* const* d_in, const int* in_sizes, int n_in,
                              void* d_out, int out_size) {
    const float* Q = (const float*)d_in[0];
    const float* K = (const float*)d_in[1];
    const float* V = (const float*)d_in[2];
    float* Out = (float*)d_out;

    const int BS = in_sizes[0] / (HQ * DHEAD);  // B * S
    const int B = 2;                            // fixed by the reference
    const int S = BS / B;
    const int nblk = S / BLK;

    cudaFuncSetAttribute(fa_swa_kernel,
                         cudaFuncAttributeMaxDynamicSharedMemorySize, SMEM_BYTES);

    dim3 grid(nblk, HQ, B);
    fa_swa_kernel<<<grid, NTHREADS, SMEM_BYTES>>>(Q, K, V, Out, S);
}